// round 16
// baseline (speedup 1.0000x reference)
#include <cuda_runtime.h>

#define B_DIM 256
#define N_DIM 256
#define EPS_F 1e-7f
#define TAU   0.1f

// Scratch (no allocations allowed anywhere)
__device__ float2       g_tf[B_DIM];
__device__ unsigned int g_ticket;

__device__ __forceinline__ float poly_mlog1m(float x) {
    // Sum_{m=1..3} x^m/m (approximates -log(1-x); row truncation <= 2.5e-4 abs)
    return x * fmaf(x, fmaf(x, 1.0f / 3.0f, 0.5f), 1.0f);
}

// -----------------------------------------------------------------------------
// One block per batch row, 256 threads. FINAL configuration (round-15 winner
// + own-run search replaced by a warp match):
//  * key = (ordered tm bits << 32) | float_bits(e); warp bitonic sort -> 8 runs
//  * each thread processes the element it HOLDS post-sort; tm_s/e_s/u_s unpack
//    from the key register
//  * per-run register suffix scan of (e, e^2, e^3) -> 33-entry tables
//  * den3 = sum over runs of suffix[count_less(u_s)]; for the OWN run,
//    count_less = lane - (#equal-u at lower lanes) via __match_any_sync —
//    no dependent-LDS chain. Strict tm-bit compare keeps equal-tm ties in the
//    suffix (reference T_j >= T_i, exact).
//  * part1 fused with self-log: log(den) - p == -log(e_s*id) (one MUFU log);
//    series first term den/den folded to 1
//  * part2 = 3-term series - poly(x_self) + exact-log corrections for rare
//    pairs with e_k/den > TAU (superset flag e_k > TAU*den_k)
//  * warp-0 ticket + warp-local deterministic final reduction
// Barriers: 3.
// -----------------------------------------------------------------------------
__global__ void __launch_bounds__(N_DIM) cox_kernel(
    const float* __restrict__ pred,
    const float* __restrict__ target,
    const unsigned int* __restrict__ mask,
    float* __restrict__ out)
{
    const int b = blockIdx.x;
    const int i = threadIdx.x;
    const int base = b * N_DIM;
    const int lane = i & 31, w8 = i >> 5;

    __shared__ unsigned int skey32[N_DIM];   // sorted tm-keys (8 runs of 32)
    __shared__ float4       srun[8 * 33];    // per-run suffix sums + sentinel
    __shared__ unsigned int s_runmax[8];     // per-run max tm key (ordered uint)
    __shared__ float2       candTE[N_DIM];   // per-warp candidate regions
    __shared__ int          candI[N_DIM];
    __shared__ int          warp_cc[8];
    __shared__ int          warp_vc[8];
    __shared__ float        sredA[8];

    // Loads (mask elements are 4-byte; !=0 covers int and float encodings)
    const float p  = pred[base + i];
    const float t  = target[base + i];
    const bool  v  = mask[base + i] != 0u;

    const float tm = v ? t : -1.0f;
    const float e  = __expf(p);

    // Per-warp valid count (read only after bar3)
    {
        const unsigned int bv = __ballot_sync(0xffffffffu, v);
        if (lane == 0) warp_vc[w8] = __popc(bv);
    }

    // Order-preserving tm key (invalid -1 below valid >= 0); payload in low 32
    const unsigned int fb = __float_as_uint(tm);
    const unsigned int u  = fb ^ ((fb & 0x80000000u) ? 0xFFFFFFFFu : 0x80000000u);
    unsigned long long key = ((unsigned long long)u << 32) | __float_as_uint(e);

    // Warp bitonic sort, ascending across lanes (15 compare-exchange stages)
    #pragma unroll
    for (int k = 2; k <= 32; k <<= 1) {
        #pragma unroll
        for (int j = k >> 1; j > 0; j >>= 1) {
            const unsigned long long other = __shfl_xor_sync(0xffffffffu, key, j);
            const bool keepmin = (((lane & j) == 0) == ((lane & k) == 0));
            const bool gt = key > other;
            key = (gt == keepmin) ? other : key;
        }
    }

    // This thread now OWNS the sorted element: unpack it once.
    const unsigned int u_s = (unsigned int)(key >> 32);
    const float        e_s = __uint_as_float((unsigned int)key);
    const unsigned int fs  = (u_s & 0x80000000u) ? (u_s ^ 0x80000000u) : ~u_s;
    const float        tm_s = __uint_as_float(fs);

    // Own-run count_less: lane minus equal-u elements at lower lanes.
    const unsigned int eqmask = __match_any_sync(0xffffffffu, u_s);
    const int own_lo = lane - __popc(eqmask & ((1u << lane) - 1u));

    // Per-run register suffix scan of (e, e^2, e^3) over sorted order
    {
        const float e2 = e_s * e_s;
        float3 x = make_float3(e_s, e2, e2 * e_s);
        #pragma unroll
        for (int o = 1; o < 32; o <<= 1) {
            const float t0 = __shfl_down_sync(0xffffffffu, x.x, o);
            const float t1 = __shfl_down_sync(0xffffffffu, x.y, o);
            const float t2 = __shfl_down_sync(0xffffffffu, x.z, o);
            if (lane < 32 - o) { x.x += t0; x.y += t1; x.z += t2; }
        }
        skey32[i] = u_s;
        srun[w8 * 33 + lane] = make_float4(x.x, x.y, x.z, 0.0f);
        if (lane == 31) {
            srun[w8 * 33 + 32] = make_float4(0.f, 0.f, 0.f, 0.f);
            s_runmax[w8] = u_s;                        // run max (ordered uint)
        }
    }
    __syncthreads();                                   // bar1

    // den3 = sum over runs of suffix at count_less(u_s): all tm_j >= tm_s
    float3 den3;
    {
        const float4 S0 = srun[w8 * 33 + own_lo];      // own run: direct index
        den3 = make_float3(S0.x, S0.y, S0.z);
    }
    #pragma unroll
    for (int w = 0; w < 8; ++w) {
        if (w == w8) continue;                         // own run handled above
        const int rb = w * 32;
        int lo = 0;
        #pragma unroll
        for (int s = 16; s; s >>= 1)
            if (skey32[rb + lo + s - 1] < u_s) lo += s;
        lo += (int)(skey32[rb + lo] < u_s);            // resolve 31 vs 32
        const float4 S = srun[w * 33 + lo];
        den3.x += S.x; den3.y += S.y; den3.z += S.z;
    }
    const float den = den3.x;

    unsigned int ubmax = s_runmax[0];
    #pragma unroll
    for (int w = 1; w < 8; ++w) ubmax = max(ubmax, s_runmax[w]);
    const unsigned int fbm = (ubmax & 0x80000000u) ? (ubmax ^ 0x80000000u) : ~ubmax;
    const float bmax = __uint_as_float(fbm);

    // Candidates (x > TAU superset: den_i >= den_k for k in risk(i)), per-warp
    {
        const bool flag = (tm_s > 0.0f) && (e_s > TAU * den);
        const unsigned int bal = __ballot_sync(0xffffffffu, flag);
        if (lane == 0) warp_cc[w8] = __popc(bal);
        if (flag) {
            const int pos = __popc(bal & ((1u << lane) - 1u));
            candTE[w8 * 32 + pos] = make_float2(tm_s, e_s);
            candI [w8 * 32 + pos] = i;
        }
    }
    __syncthreads();                                   // bar2

    // Contribution of the sorted element
    float contrib = 0.0f;
    const bool elim = (tm_s > 0.0f) && (tm_s < bmax);
    if (elim) {
        const float id  = __fdividef(1.0f, den);
        const float id2 = id * id;
        const float xs  = e_s * id;                    // self x
        // Series: Sum_k x_k = den/den = 1 exactly; higher terms from suffix sums
        float part2 = 1.0f + 0.5f * (den3.y * id2)
                    + (1.0f / 3.0f) * (den3.z * (id2 * id));
        part2 -= poly_mlog1m(xs);                      // remove self term

        // Exact-log corrections (rare; skip the scan when block has none)
        int Q = 0;
        #pragma unroll
        for (int w = 0; w < 8; ++w) Q += warp_cc[w];
        if (Q) {
            #pragma unroll
            for (int w = 0; w < 8; ++w) {
                const int nw = warp_cc[w];
                for (int q = 0; q < nw; ++q) {
                    const float2 te = candTE[w * 32 + q];
                    const float xx = te.y * id;
                    if (te.x >= tm_s && xx > TAU && candI[w * 32 + q] != i)
                        contrib += -__logf(fmaxf(1.0f + EPS_F - xx, 2.0f * EPS_F))
                                   - poly_mlog1m(xx);
                }
            }
        }
        const float w = fminf(fmaxf((bmax - tm_s) / fmaxf(bmax, 1.0f), 0.0f), 1.0f);
        // part1 fused: log(den) - p == -log(e_s/den) (e_s = fl(exp(p)))
        contrib = (-__logf(xs) + part2 + contrib) * w;
    }

    // Block reduce -> g_tf[b]
    #pragma unroll
    for (int o = 16; o > 0; o >>= 1)
        contrib += __shfl_xor_sync(0xffffffffu, contrib, o);
    if (lane == 0) sredA[w8] = contrib;
    __syncthreads();                                   // bar3

    // Warp 0 finishes: publish row result; last ticket-holder reduces all rows
    if (w8 == 0) {
        unsigned int tk = 0;
        if (lane == 0) {
            float s = 0.0f;
            int vcnt = 0;
            #pragma unroll
            for (int k = 0; k < 8; ++k) { s += sredA[k]; vcnt += warp_vc[k]; }
            const float flagv = (vcnt >= 2) ? 1.0f : 0.0f;
            g_tf[b] = make_float2(s * flagv, flagv);
            __threadfence();
            tk = atomicAdd(&g_ticket, 1u);
        }
        tk = __shfl_sync(0xffffffffu, tk, 0);
        if (tk == (unsigned int)gridDim.x - 1u) {      // last block's warp 0
            if (lane == 0) g_ticket = 0;               // reset for next replay
            __threadfence();
            float T = 0.0f, F = 0.0f;
            #pragma unroll
            for (int k = 0; k < 8; ++k) {              // fixed order: deterministic
                const float2 tf = g_tf[lane * 8 + k];
                T += tf.x; F += tf.y;
            }
            #pragma unroll
            for (int o = 16; o > 0; o >>= 1) {
                T += __shfl_xor_sync(0xffffffffu, T, o);
                F += __shfl_xor_sync(0xffffffffu, F, o);
            }
            if (lane == 0) out[0] = T / fmaxf(F, 1.0f);
        }
    }
}

extern "C" void kernel_launch(void* const* d_in, const int* in_sizes, int n_in,
                              void* d_out, int out_size) {
    (void)in_sizes; (void)n_in; (void)out_size;
    const float*        pred   = (const float*)d_in[0];
    const float*        target = (const float*)d_in[1];
    const unsigned int* mask   = (const unsigned int*)d_in[2];

    cox_kernel<<<B_DIM, N_DIM>>>(pred, target, mask, (float*)d_out);
}

// round 17
// speedup vs baseline: 1.2149x; 1.2149x over previous
#include <cuda_runtime.h>

#define B_DIM 256
#define N_DIM 256
#define EPS_F 1e-7f
#define TAU   0.1f

// Scratch (no allocations allowed anywhere)
__device__ float2       g_tf[B_DIM];
__device__ unsigned int g_ticket;

__device__ __forceinline__ float poly_mlog1m(float x) {
    // Sum_{m=1..3} x^m/m (approximates -log(1-x); row truncation <= 2.5e-4 abs)
    return x * fmaf(x, fmaf(x, 1.0f / 3.0f, 0.5f), 1.0f);
}

// -----------------------------------------------------------------------------
// One block per batch row, 256 threads. FINAL — measured-best configuration
// (round 15: 9.54 us kernel / 10.72 us total). Sorted-element perspective:
//  * key = (ordered tm bits << 32) | float_bits(e); warp bitonic sort -> 8 runs
//  * each thread processes the element it HOLDS post-sort; tm_s/e_s/u_s unpack
//    from the key register (no payload recovery, no staging arrays)
//  * per-run register suffix scan of (e, e^2, e^3) -> 33-entry tables
//  * den3 = sum over runs of suffix[count_less(u_s)]; strict tm-bit compare
//    keeps all equal-tm ties in the suffix (reference T_j >= T_i, exact)
//  * part1 fused with self-log: log(den) - p == -log(e_s*id) (one MUFU log);
//    series first term den/den folded to the constant 1
//  * part2 = 3-term series - poly(x_self) + exact-log corrections for rare
//    pairs with e_k/den > TAU (superset flag e_k > TAU*den_k)
//  * warp-0 ticket + warp-local deterministic final reduction
// Barriers: 3.
// -----------------------------------------------------------------------------
__global__ void __launch_bounds__(N_DIM) cox_kernel(
    const float* __restrict__ pred,
    const float* __restrict__ target,
    const unsigned int* __restrict__ mask,
    float* __restrict__ out)
{
    const int b = blockIdx.x;
    const int i = threadIdx.x;
    const int base = b * N_DIM;
    const int lane = i & 31, w8 = i >> 5;

    __shared__ unsigned int skey32[N_DIM];   // sorted tm-keys (8 runs of 32)
    __shared__ float4       srun[8 * 33];    // per-run suffix sums + sentinel
    __shared__ unsigned int s_runmax[8];     // per-run max tm key (ordered uint)
    __shared__ float2       candTE[N_DIM];   // per-warp candidate regions
    __shared__ int          candI[N_DIM];
    __shared__ int          warp_cc[8];
    __shared__ int          warp_vc[8];
    __shared__ float        sredA[8];

    // Loads (mask elements are 4-byte; !=0 covers int and float encodings)
    const float p  = pred[base + i];
    const float t  = target[base + i];
    const bool  v  = mask[base + i] != 0u;

    const float tm = v ? t : -1.0f;
    const float e  = __expf(p);

    // Per-warp valid count (read only after bar3)
    {
        const unsigned int bv = __ballot_sync(0xffffffffu, v);
        if (lane == 0) warp_vc[w8] = __popc(bv);
    }

    // Order-preserving tm key (invalid -1 below valid >= 0); payload in low 32
    const unsigned int fb = __float_as_uint(tm);
    const unsigned int u  = fb ^ ((fb & 0x80000000u) ? 0xFFFFFFFFu : 0x80000000u);
    unsigned long long key = ((unsigned long long)u << 32) | __float_as_uint(e);

    // Warp bitonic sort, ascending across lanes (15 compare-exchange stages)
    #pragma unroll
    for (int k = 2; k <= 32; k <<= 1) {
        #pragma unroll
        for (int j = k >> 1; j > 0; j >>= 1) {
            const unsigned long long other = __shfl_xor_sync(0xffffffffu, key, j);
            const bool keepmin = (((lane & j) == 0) == ((lane & k) == 0));
            const bool gt = key > other;
            key = (gt == keepmin) ? other : key;
        }
    }

    // This thread now OWNS the sorted element: unpack it once.
    const unsigned int u_s = (unsigned int)(key >> 32);
    const float        e_s = __uint_as_float((unsigned int)key);
    const unsigned int fs  = (u_s & 0x80000000u) ? (u_s ^ 0x80000000u) : ~u_s;
    const float        tm_s = __uint_as_float(fs);

    // Per-run register suffix scan of (e, e^2, e^3) over sorted order
    {
        const float e2 = e_s * e_s;
        float3 x = make_float3(e_s, e2, e2 * e_s);
        #pragma unroll
        for (int o = 1; o < 32; o <<= 1) {
            const float t0 = __shfl_down_sync(0xffffffffu, x.x, o);
            const float t1 = __shfl_down_sync(0xffffffffu, x.y, o);
            const float t2 = __shfl_down_sync(0xffffffffu, x.z, o);
            if (lane < 32 - o) { x.x += t0; x.y += t1; x.z += t2; }
        }
        skey32[i] = u_s;
        srun[w8 * 33 + lane] = make_float4(x.x, x.y, x.z, 0.0f);
        if (lane == 31) {
            srun[w8 * 33 + 32] = make_float4(0.f, 0.f, 0.f, 0.f);
            s_runmax[w8] = u_s;                        // run max (ordered uint)
        }
    }
    __syncthreads();                                   // bar1

    // den3 = sum over runs of suffix at count_less(u_s): all tm_j >= tm_s
    float3 den3 = make_float3(0.f, 0.f, 0.f);
    #pragma unroll
    for (int w = 0; w < 8; ++w) {
        const int rb = w * 32;
        int lo = 0;
        #pragma unroll
        for (int s = 16; s; s >>= 1)
            if (skey32[rb + lo + s - 1] < u_s) lo += s;
        lo += (int)(skey32[rb + lo] < u_s);            // resolve 31 vs 32
        const float4 S = srun[w * 33 + lo];
        den3.x += S.x; den3.y += S.y; den3.z += S.z;
    }
    const float den = den3.x;

    unsigned int ubmax = s_runmax[0];
    #pragma unroll
    for (int w = 1; w < 8; ++w) ubmax = max(ubmax, s_runmax[w]);
    const unsigned int fbm = (ubmax & 0x80000000u) ? (ubmax ^ 0x80000000u) : ~ubmax;
    const float bmax = __uint_as_float(fbm);

    // Candidates (x > TAU superset: den_i >= den_k for k in risk(i)), per-warp
    {
        const bool flag = (tm_s > 0.0f) && (e_s > TAU * den);
        const unsigned int bal = __ballot_sync(0xffffffffu, flag);
        if (lane == 0) warp_cc[w8] = __popc(bal);
        if (flag) {
            const int pos = __popc(bal & ((1u << lane) - 1u));
            candTE[w8 * 32 + pos] = make_float2(tm_s, e_s);
            candI [w8 * 32 + pos] = i;
        }
    }
    __syncthreads();                                   // bar2

    // Contribution of the sorted element
    float contrib = 0.0f;
    const bool elim = (tm_s > 0.0f) && (tm_s < bmax);
    if (elim) {
        const float id  = __fdividef(1.0f, den);
        const float id2 = id * id;
        const float xs  = e_s * id;                    // self x
        // Series: Sum_k x_k = den/den = 1 exactly; higher terms from suffix sums
        float part2 = 1.0f + 0.5f * (den3.y * id2)
                    + (1.0f / 3.0f) * (den3.z * (id2 * id));
        part2 -= poly_mlog1m(xs);                      // remove self term

        // Exact-log corrections (rare; skip the scan when block has none)
        int Q = 0;
        #pragma unroll
        for (int w = 0; w < 8; ++w) Q += warp_cc[w];
        if (Q) {
            #pragma unroll
            for (int w = 0; w < 8; ++w) {
                const int nw = warp_cc[w];
                for (int q = 0; q < nw; ++q) {
                    const float2 te = candTE[w * 32 + q];
                    const float xx = te.y * id;
                    if (te.x >= tm_s && xx > TAU && candI[w * 32 + q] != i)
                        contrib += -__logf(fmaxf(1.0f + EPS_F - xx, 2.0f * EPS_F))
                                   - poly_mlog1m(xx);
                }
            }
        }
        const float w = fminf(fmaxf((bmax - tm_s) / fmaxf(bmax, 1.0f), 0.0f), 1.0f);
        // part1 fused: log(den) - p == -log(e_s/den) (e_s = fl(exp(p)))
        contrib = (-__logf(xs) + part2 + contrib) * w;
    }

    // Block reduce -> g_tf[b]
    #pragma unroll
    for (int o = 16; o > 0; o >>= 1)
        contrib += __shfl_xor_sync(0xffffffffu, contrib, o);
    if (lane == 0) sredA[w8] = contrib;
    __syncthreads();                                   // bar3

    // Warp 0 finishes: publish row result; last ticket-holder reduces all rows
    if (w8 == 0) {
        unsigned int tk = 0;
        if (lane == 0) {
            float s = 0.0f;
            int vcnt = 0;
            #pragma unroll
            for (int k = 0; k < 8; ++k) { s += sredA[k]; vcnt += warp_vc[k]; }
            const float flagv = (vcnt >= 2) ? 1.0f : 0.0f;
            g_tf[b] = make_float2(s * flagv, flagv);
            __threadfence();
            tk = atomicAdd(&g_ticket, 1u);
        }
        tk = __shfl_sync(0xffffffffu, tk, 0);
        if (tk == (unsigned int)gridDim.x - 1u) {      // last block's warp 0
            if (lane == 0) g_ticket = 0;               // reset for next replay
            __threadfence();
            float T = 0.0f, F = 0.0f;
            #pragma unroll
            for (int k = 0; k < 8; ++k) {              // fixed order: deterministic
                const float2 tf = g_tf[lane * 8 + k];
                T += tf.x; F += tf.y;
            }
            #pragma unroll
            for (int o = 16; o > 0; o >>= 1) {
                T += __shfl_xor_sync(0xffffffffu, T, o);
                F += __shfl_xor_sync(0xffffffffu, F, o);
            }
            if (lane == 0) out[0] = T / fmaxf(F, 1.0f);
        }
    }
}

extern "C" void kernel_launch(void* const* d_in, const int* in_sizes, int n_in,
                              void* d_out, int out_size) {
    (void)in_sizes; (void)n_in; (void)out_size;
    const float*        pred   = (const float*)d_in[0];
    const float*        target = (const float*)d_in[1];
    const unsigned int* mask   = (const unsigned int*)d_in[2];

    cox_kernel<<<B_DIM, N_DIM>>>(pred, target, mask, (float*)d_out);
}